// round 12
// baseline (speedup 1.0000x reference)
#include <cuda_runtime.h>

#define N_UNITS 8
#define M_ATOMS 1024
#define N_PAIRS 28
#define LOG2E 1.4426950408889634f
#define ALPHA 1.0f
#define LAMBDA1 0.5f

// fused kernel tiling
#define TPB 128
#define I_PER_THREAD 2
#define ITILE (TPB * I_PER_THREAD)     // 256
#define JTILE 128
#define NJJ (JTILE / 2)                // 64 packed iterations
#define TILES_PER_PAIR ((M_ATOMS / ITILE) * (M_ATOMS / JTILE))  // 4*8 = 32
#define PAIR_CTAS (N_PAIRS * TILES_PER_PAIR)                    // 896

// table-exp constants: m = round(256*s) captured via float bias
#define BIAS_F    49152.0f      // 1.5 * 2^15 -> quantizes to 2^-8
#define BIAS_BITS 0x47400000
#define M_CLAMP   (-32256)      // n >= -126

// ---------------- device scratch (allocation-free, stateless) ----------------
__device__ float g_part[PAIR_CTAS];

__constant__ unsigned char c_pa[N_PAIRS] =
    {0,0,0,0,0,0,0,1,1,1,1,1,1,2,2,2,2,2,3,3,3,3,4,4,4,5,5,6};
__constant__ unsigned char c_pb[N_PAIRS] =
    {1,2,3,4,5,6,7,2,3,4,5,6,7,3,4,5,6,7,4,5,6,7,5,6,7,6,7,7};

// ---------------- helpers ----------------
__device__ __forceinline__ float ex2_approx(float x) {
    float y;
    asm("ex2.approx.ftz.f32 %0, %1;" : "=f"(y) : "f"(x));
    return y;
}
__device__ __forceinline__ unsigned long long pack2(float a, float b) {
    unsigned long long r;
    asm("mov.b64 %0, {%1, %2};" : "=l"(r) : "f"(a), "f"(b));
    return r;
}
__device__ __forceinline__ void unpack2(unsigned long long p, float& lo, float& hi) {
    asm("mov.b64 {%0, %1}, %2;" : "=f"(lo), "=f"(hi) : "l"(p));
}
__device__ __forceinline__ unsigned long long fma2(unsigned long long a,
                                                   unsigned long long b,
                                                   unsigned long long c) {
    unsigned long long d;
    asm("fma.rn.f32x2 %0, %1, %2, %3;" : "=l"(d) : "l"(a), "l"(b), "l"(c));
    return d;
}

// ---------------- kernel 1: fused pair compute ----------------
// 896 CTAs x 128 threads. CTA = (pair, iTile, jTile). Writes g_part[bid].
// exp split: i0's 2 exps per iter on MUFU, i1's 2 exps via smem table
// (ALU+LSU pipes). E_i = 2^{h_i} factored out of the j-loop.
__global__ void __launch_bounds__(TPB) k_fused(const float* __restrict__ pos,
                                               const float* __restrict__ eul,
                                               const float* __restrict__ coord)
{
    __shared__ float sM[N_UNITS][12];                 // R(9) + pos(3) per unit
    __shared__ __align__(16) float svp[NJJ][4][2];    // packed j tile, 2KB
    __shared__ int  sTbl[256];                        // 2^{idx/256} bit patterns
    __shared__ float ws[TPB / 32];

    int tid = threadIdx.x;
    int bid = blockIdx.x;

    int pairIdx = bid >> 5;          // 32 tiles per pair
    int rem     = bid & 31;
    int iTile   = rem >> 3;          // 0..3
    int jTile   = rem & 7;           // 0..7
    int a = c_pa[pairIdx];
    int b = c_pb[pairIdx];

    // ---- table build (all threads) + rotation matrices (8 lanes) ----
    sTbl[tid]       = __float_as_int(ex2_approx((float)tid       * (1.0f / 256.0f)));
    sTbl[tid + 128] = __float_as_int(ex2_approx((float)(tid+128) * (1.0f / 256.0f)));

    if (tid < N_UNITS) {
        int n = tid;
        float phi   = eul[3 * n + 0];
        float theta = eul[3 * n + 1];
        float psi   = eul[3 * n + 2];
        float sp, cp, st, ct, ss, cs;
        sincosf(phi,   &sp, &cp);
        sincosf(theta, &st, &ct);
        sincosf(psi,   &ss, &cs);
        sM[n][0] = cs * ct;
        sM[n][1] = cs * st * sp - ss * cp;
        sM[n][2] = cs * st * cp + ss * sp;
        sM[n][3] = ss * ct;
        sM[n][4] = ss * st * sp + cs * cp;
        sM[n][5] = ss * st * cp - cs * sp;
        sM[n][6] = -st;
        sM[n][7] = ct * sp;
        sM[n][8] = ct * cp;
        sM[n][9]  = pos[3 * n + 0];
        sM[n][10] = pos[3 * n + 1];
        sM[n][11] = pos[3 * n + 2];
    }
    __syncthreads();

    // ---- stage j tile (all 128 threads, one j-point each) ----
    float jsq;
    {
        int jm = jTile * JTILE + tid;
        float cx = coord[3 * jm + 0];
        float cy = coord[3 * jm + 1];
        float cz = coord[3 * jm + 2];
        float tx = fmaf(sM[b][0], cx, fmaf(sM[b][1], cy, fmaf(sM[b][2], cz, sM[b][9])));
        float ty = fmaf(sM[b][3], cx, fmaf(sM[b][4], cy, fmaf(sM[b][5], cz, sM[b][10])));
        float tz = fmaf(sM[b][6], cx, fmaf(sM[b][7], cy, fmaf(sM[b][8], cz, sM[b][11])));
        float sq = fmaf(tx, tx, fmaf(ty, ty, tz * tz));
        float h  = LOG2E * (0.5f - sq);
        int jj = tid >> 1, half = tid & 1;
        svp[jj][0][half] = tx;
        svp[jj][1][half] = ty;
        svp[jj][2][half] = tz;
        svp[jj][3][half] = h;
        jsq = sq;
    }

    // ---- transform own 2 i-points -> packed registers (no h in u) ----
    unsigned long long u0x, u0y, u0z, u1x, u1y, u1z;
    float E0, E1, isq;
    {
        int mi = iTile * ITILE + tid * I_PER_THREAD;
        float r0 = sM[a][0], r1 = sM[a][1], r2 = sM[a][2];
        float r3 = sM[a][3], r4 = sM[a][4], r5 = sM[a][5];
        float r6 = sM[a][6], r7 = sM[a][7], r8 = sM[a][8];
        float px = sM[a][9], py = sM[a][10], pz = sM[a][11];

        float cx0 = coord[3 * mi + 0], cy0 = coord[3 * mi + 1], cz0 = coord[3 * mi + 2];
        float cx1 = coord[3 * mi + 3], cy1 = coord[3 * mi + 4], cz1 = coord[3 * mi + 5];

        float tx0 = fmaf(r0, cx0, fmaf(r1, cy0, fmaf(r2, cz0, px)));
        float ty0 = fmaf(r3, cx0, fmaf(r4, cy0, fmaf(r5, cz0, py)));
        float tz0 = fmaf(r6, cx0, fmaf(r7, cy0, fmaf(r8, cz0, pz)));
        float tx1 = fmaf(r0, cx1, fmaf(r1, cy1, fmaf(r2, cz1, px)));
        float ty1 = fmaf(r3, cx1, fmaf(r4, cy1, fmaf(r5, cz1, py)));
        float tz1 = fmaf(r6, cx1, fmaf(r7, cy1, fmaf(r8, cz1, pz)));

        float sq0 = fmaf(tx0, tx0, fmaf(ty0, ty0, tz0 * tz0));
        float sq1 = fmaf(tx1, tx1, fmaf(ty1, ty1, tz1 * tz1));
        float h0  = LOG2E * (0.5f - sq0);
        float h1  = LOG2E * (0.5f - sq1);
        E0 = ex2_approx(h0);        // 2^{h_i} factored out of j-loop
        E1 = ex2_approx(h1);
        isq = sq0 + sq1;

        float s2 = 2.0f * LOG2E;
        u0x = pack2(s2 * tx0, s2 * tx0);
        u0y = pack2(s2 * ty0, s2 * ty0);
        u0z = pack2(s2 * tz0, s2 * tz0);
        u1x = pack2(s2 * tx1, s2 * tx1);
        u1y = pack2(s2 * ty1, s2 * ty1);
        u1z = pack2(s2 * tz1, s2 * tz1);
    }
    __syncthreads();

    // ---- main pair loop: seed = h_j, i0 exps on MUFU, i1 exps via table ----
    float acc0 = 0.f, acc1 = 0.f, acc2 = 0.f, acc3 = 0.f;
    const ulonglong2* __restrict__ vp = (const ulonglong2*)&svp[0][0][0];

    #pragma unroll 4
    for (int q = 0; q < NJJ; q++) {
        ulonglong2 P0 = vp[2 * q + 0];   // {xx, yy}
        ulonglong2 P1 = vp[2 * q + 1];   // {zz, hh}

        // s_partial = u . v + h_j   (h_j is the packed seed P1.y)
        unsigned long long s0 =
            fma2(u0x, P0.x, fma2(u0y, P0.y, fma2(u0z, P1.x, P1.y)));
        unsigned long long s1 =
            fma2(u1x, P0.x, fma2(u1y, P0.y, fma2(u1z, P1.x, P1.y)));

        // i0: MUFU path
        float lo0, hi0;
        unpack2(s0, lo0, hi0);
        acc0 += ex2_approx(lo0);
        acc1 += ex2_approx(hi0);

        // i1: table path  2^s = 2^n * tbl[idx],  m = round(256 s)
        float lo1, hi1;
        unpack2(s1, lo1, hi1);
        {
            int ml = __float_as_int(lo1 + BIAS_F) - BIAS_BITS;
            ml = max(ml, M_CLAMP);
            acc2 += __int_as_float(sTbl[ml & 255] + ((ml >> 8) << 23));
        }
        {
            int mh = __float_as_int(hi1 + BIAS_F) - BIAS_BITS;
            mh = max(mh, M_CLAMP);
            acc3 += __int_as_float(sTbl[mh & 255] + ((mh >> 8) << 23));
        }
    }

    // ---- fold per-thread extras, block-reduce, write partial ----
    float t = LAMBDA1 * (E0 * (acc0 + acc1) + E1 * (acc2 + acc3));
    // L1 i-side: units 0..6 owned by (b==a+1, jTile==0) CTAs
    if (b == a + 1 && jTile == 0) t += isq * (1.0f / (float)N_UNITS);
    // L1 unit 7: owned by pair (6,7), iTile==0, via j-points
    if (a == 6 && iTile == 0)     t += jsq * (1.0f / (float)N_UNITS);

    #pragma unroll
    for (int o = 16; o > 0; o >>= 1)
        t += __shfl_down_sync(0xFFFFFFFFu, t, o);

    int lane = tid & 31, wid = tid >> 5;
    if (lane == 0) ws[wid] = t;
    __syncthreads();

    if (tid == 0) {
        float s = 0.0f;
        #pragma unroll
        for (int w = 0; w < TPB / 32; w++) s += ws[w];
        g_part[bid] = s;
    }
}

// ---------------- kernel 2: finisher (1 CTA) ----------------
__global__ void __launch_bounds__(256) k_finish(const float* __restrict__ pos,
                                                float* __restrict__ out)
{
    int tid = threadIdx.x;
    float s = 0.0f;
    for (int i = tid; i < PAIR_CTAS; i += 256)
        s += g_part[i];

    #pragma unroll
    for (int o = 16; o > 0; o >>= 1)
        s += __shfl_down_sync(0xFFFFFFFFu, s, o);

    __shared__ float ws[8];
    int lane = tid & 31, wid = tid >> 5;
    if (lane == 0) ws[wid] = s;
    __syncthreads();

    if (tid == 0) {
        float tot = 0.0f;
        #pragma unroll
        for (int w = 0; w < 8; w++) tot += ws[w];
        float sx = 0.0f, sy = 0.0f, sz = 0.0f;
        #pragma unroll
        for (int k = 0; k < N_UNITS; k++) {
            sx += pos[3 * k + 0];
            sy += pos[3 * k + 1];
            sz += pos[3 * k + 2];
        }
        tot += ALPHA * (sx * sx + sy * sy + sz * sz);
        out[0] = tot;
    }
}

extern "C" void kernel_launch(void* const* d_in, const int* in_sizes, int n_in,
                              void* d_out, int out_size)
{
    const float* positions    = (const float*)d_in[0];
    const float* euler_angles = (const float*)d_in[1];
    const float* coordinates  = (const float*)d_in[2];
    float* out = (float*)d_out;
    (void)in_sizes; (void)n_in; (void)out_size;

    k_fused<<<PAIR_CTAS, TPB>>>(positions, euler_angles, coordinates);
    k_finish<<<1, 256>>>(positions, out);
}

// round 13
// speedup vs baseline: 1.0135x; 1.0135x over previous
#include <cuda_runtime.h>

#define N_UNITS 8
#define M_ATOMS 1024
#define N_PAIRS 28
#define LOG2E 1.4426950408889634f
#define ALPHA 1.0f
#define LAMBDA1 0.5f

// fused kernel tiling
#define TPB 128
#define I_PER_THREAD 2
#define ITILE (TPB * I_PER_THREAD)     // 256
#define JTILE 128
#define NJJ (JTILE / 2)                // 64 packed iterations
#define TILES_PER_PAIR ((M_ATOMS / ITILE) * (M_ATOMS / JTILE))  // 4*8 = 32
#define PAIR_CTAS (N_PAIRS * TILES_PER_PAIR)                    // 896

// ---------------- device scratch (allocation-free) ----------------
// g_acc: zero-initialized; k_fused CTAs atomicAdd into it; k_finish publishes
// it to out[0] and resets it to 0 via atomicExch -> net-zero across a replay.
__device__ float g_acc;

__constant__ unsigned char c_pa[N_PAIRS] =
    {0,0,0,0,0,0,0,1,1,1,1,1,1,2,2,2,2,2,3,3,3,3,4,4,4,5,5,6};
__constant__ unsigned char c_pb[N_PAIRS] =
    {1,2,3,4,5,6,7,2,3,4,5,6,7,3,4,5,6,7,4,5,6,7,5,6,7,6,7,7};

// ---------------- helpers ----------------
__device__ __forceinline__ float ex2_approx(float x) {
    float y;
    asm("ex2.approx.ftz.f32 %0, %1;" : "=f"(y) : "f"(x));
    return y;
}
__device__ __forceinline__ unsigned long long pack2(float a, float b) {
    unsigned long long r;
    asm("mov.b64 %0, {%1, %2};" : "=l"(r) : "f"(a), "f"(b));
    return r;
}
__device__ __forceinline__ void unpack2(unsigned long long p, float& lo, float& hi) {
    asm("mov.b64 {%0, %1}, %2;" : "=f"(lo), "=f"(hi) : "l"(p));
}
__device__ __forceinline__ unsigned long long fma2(unsigned long long a,
                                                   unsigned long long b,
                                                   unsigned long long c) {
    unsigned long long d;
    asm("fma.rn.f32x2 %0, %1, %2, %3;" : "=l"(d) : "l"(a), "l"(b), "l"(c));
    return d;
}

// ---------------- kernel 1: fused pair compute ----------------
// 896 CTAs x 128 threads. CTA = (pair, iTile, jTile).
// Pure-MUFU exp (proven optimum) with E_i = 2^{h_i} factored out of the
// j-loop: s = u.v + h_j, pen = E_i * 2^s. 6 f32x2 + 4 MUFU per 4 pairs.
__global__ void __launch_bounds__(TPB) k_fused(const float* __restrict__ pos,
                                               const float* __restrict__ eul,
                                               const float* __restrict__ coord)
{
    __shared__ float sM[N_UNITS][12];                 // R(9) + pos(3) per unit
    __shared__ __align__(16) float svp[NJJ][4][2];    // packed j tile, 2KB
    __shared__ float ws[TPB / 32];

    int tid = threadIdx.x;
    int bid = blockIdx.x;

    int pairIdx = bid >> 5;          // 32 tiles per pair
    int rem     = bid & 31;
    int iTile   = rem >> 3;          // 0..3
    int jTile   = rem & 7;           // 0..7
    int a = c_pa[pairIdx];
    int b = c_pb[pairIdx];

    // ---- rotation matrices (8 lanes of warp 0) ----
    if (tid < N_UNITS) {
        int n = tid;
        float phi   = eul[3 * n + 0];
        float theta = eul[3 * n + 1];
        float psi   = eul[3 * n + 2];
        float sp, cp, st, ct, ss, cs;
        sincosf(phi,   &sp, &cp);
        sincosf(theta, &st, &ct);
        sincosf(psi,   &ss, &cs);
        sM[n][0] = cs * ct;
        sM[n][1] = cs * st * sp - ss * cp;
        sM[n][2] = cs * st * cp + ss * sp;
        sM[n][3] = ss * ct;
        sM[n][4] = ss * st * sp + cs * cp;
        sM[n][5] = ss * st * cp - cs * sp;
        sM[n][6] = -st;
        sM[n][7] = ct * sp;
        sM[n][8] = ct * cp;
        sM[n][9]  = pos[3 * n + 0];
        sM[n][10] = pos[3 * n + 1];
        sM[n][11] = pos[3 * n + 2];
    }
    __syncthreads();

    // ---- stage j tile (all 128 threads, one j-point each) ----
    float jsq;
    {
        int jm = jTile * JTILE + tid;
        float cx = coord[3 * jm + 0];
        float cy = coord[3 * jm + 1];
        float cz = coord[3 * jm + 2];
        float tx = fmaf(sM[b][0], cx, fmaf(sM[b][1], cy, fmaf(sM[b][2], cz, sM[b][9])));
        float ty = fmaf(sM[b][3], cx, fmaf(sM[b][4], cy, fmaf(sM[b][5], cz, sM[b][10])));
        float tz = fmaf(sM[b][6], cx, fmaf(sM[b][7], cy, fmaf(sM[b][8], cz, sM[b][11])));
        float sq = fmaf(tx, tx, fmaf(ty, ty, tz * tz));
        float h  = LOG2E * (0.5f - sq);
        int jj = tid >> 1, half = tid & 1;
        svp[jj][0][half] = tx;
        svp[jj][1][half] = ty;
        svp[jj][2][half] = tz;
        svp[jj][3][half] = h;
        jsq = sq;
    }

    // ---- transform own 2 i-points -> packed registers ----
    unsigned long long u0x, u0y, u0z, u1x, u1y, u1z;
    float E0, E1, isq;
    {
        int mi = iTile * ITILE + tid * I_PER_THREAD;
        float r0 = sM[a][0], r1 = sM[a][1], r2 = sM[a][2];
        float r3 = sM[a][3], r4 = sM[a][4], r5 = sM[a][5];
        float r6 = sM[a][6], r7 = sM[a][7], r8 = sM[a][8];
        float px = sM[a][9], py = sM[a][10], pz = sM[a][11];

        float cx0 = coord[3 * mi + 0], cy0 = coord[3 * mi + 1], cz0 = coord[3 * mi + 2];
        float cx1 = coord[3 * mi + 3], cy1 = coord[3 * mi + 4], cz1 = coord[3 * mi + 5];

        float tx0 = fmaf(r0, cx0, fmaf(r1, cy0, fmaf(r2, cz0, px)));
        float ty0 = fmaf(r3, cx0, fmaf(r4, cy0, fmaf(r5, cz0, py)));
        float tz0 = fmaf(r6, cx0, fmaf(r7, cy0, fmaf(r8, cz0, pz)));
        float tx1 = fmaf(r0, cx1, fmaf(r1, cy1, fmaf(r2, cz1, px)));
        float ty1 = fmaf(r3, cx1, fmaf(r4, cy1, fmaf(r5, cz1, py)));
        float tz1 = fmaf(r6, cx1, fmaf(r7, cy1, fmaf(r8, cz1, pz)));

        float sq0 = fmaf(tx0, tx0, fmaf(ty0, ty0, tz0 * tz0));
        float sq1 = fmaf(tx1, tx1, fmaf(ty1, ty1, tz1 * tz1));
        float h0  = LOG2E * (0.5f - sq0);
        float h1  = LOG2E * (0.5f - sq1);
        E0 = ex2_approx(h0);        // 2^{h_i} factored out of j-loop
        E1 = ex2_approx(h1);
        isq = sq0 + sq1;

        float s2 = 2.0f * LOG2E;
        u0x = pack2(s2 * tx0, s2 * tx0);
        u0y = pack2(s2 * ty0, s2 * ty0);
        u0z = pack2(s2 * tz0, s2 * tz0);
        u1x = pack2(s2 * tx1, s2 * tx1);
        u1y = pack2(s2 * ty1, s2 * ty1);
        u1z = pack2(s2 * tz1, s2 * tz1);
    }
    __syncthreads();

    // ---- main pair loop: s = u.v + h_j, all exps on MUFU ----
    float acc0 = 0.f, acc1 = 0.f, acc2 = 0.f, acc3 = 0.f;
    const ulonglong2* __restrict__ vp = (const ulonglong2*)&svp[0][0][0];

    #pragma unroll 4
    for (int q = 0; q < NJJ; q++) {
        ulonglong2 P0 = vp[2 * q + 0];   // {xx, yy}
        ulonglong2 P1 = vp[2 * q + 1];   // {zz, hh}

        unsigned long long s0 =
            fma2(u0x, P0.x, fma2(u0y, P0.y, fma2(u0z, P1.x, P1.y)));
        unsigned long long s1 =
            fma2(u1x, P0.x, fma2(u1y, P0.y, fma2(u1z, P1.x, P1.y)));

        float lo0, hi0, lo1, hi1;
        unpack2(s0, lo0, hi0);
        unpack2(s1, lo1, hi1);
        acc0 += ex2_approx(lo0);
        acc1 += ex2_approx(hi0);
        acc2 += ex2_approx(lo1);
        acc3 += ex2_approx(hi1);
    }

    // ---- fold per-thread extras, block-reduce, atomic into g_acc ----
    float t = LAMBDA1 * (E0 * (acc0 + acc1) + E1 * (acc2 + acc3));
    // L1 i-side: units 0..6 owned by (b==a+1, jTile==0) CTAs
    if (b == a + 1 && jTile == 0) t += isq * (1.0f / (float)N_UNITS);
    // L1 unit 7: owned by pair (6,7), iTile==0, via j-points
    if (a == 6 && iTile == 0)     t += jsq * (1.0f / (float)N_UNITS);

    #pragma unroll
    for (int o = 16; o > 0; o >>= 1)
        t += __shfl_down_sync(0xFFFFFFFFu, t, o);

    int lane = tid & 31, wid = tid >> 5;
    if (lane == 0) ws[wid] = t;
    __syncthreads();

    if (tid == 0) {
        float s = 0.0f;
        #pragma unroll
        for (int w = 0; w < TPB / 32; w++) s += ws[w];
        if (bid == 0) {
            // L_com
            float sx = 0.0f, sy = 0.0f, sz = 0.0f;
            #pragma unroll
            for (int k = 0; k < N_UNITS; k++) {
                sx += pos[3 * k + 0];
                sy += pos[3 * k + 1];
                sz += pos[3 * k + 2];
            }
            s += ALPHA * (sx * sx + sy * sy + sz * sz);
        }
        atomicAdd(&g_acc, s);
    }
}

// ---------------- kernel 2: finisher (1 thread) ----------------
// Publishes the accumulated total and resets g_acc to 0 for the next replay.
__global__ void k_finish(float* __restrict__ out)
{
    out[0] = atomicExch(&g_acc, 0.0f);
}

extern "C" void kernel_launch(void* const* d_in, const int* in_sizes, int n_in,
                              void* d_out, int out_size)
{
    const float* positions    = (const float*)d_in[0];
    const float* euler_angles = (const float*)d_in[1];
    const float* coordinates  = (const float*)d_in[2];
    float* out = (float*)d_out;
    (void)in_sizes; (void)n_in; (void)out_size;

    k_fused<<<PAIR_CTAS, TPB>>>(positions, euler_angles, coordinates);
    k_finish<<<1, 1>>>(out);
}